// round 7
// baseline (speedup 1.0000x reference)
#include <cuda_runtime.h>
#include <cuda.h>
#include <cstdint>

// ============================================================================
// PHM8Linear: out[131072,512] = X[131072,512] @ H[512,512]^T + bias
// H[a*64+b][c*64+d] = sum_i A[i,a,c] * S[i,b,d]
// tcgen05 TF32 SS GEMM, persistent grid=148.
// Two M=128 sub-tiles (A: TMEM cols 0-255, B: 256-511) staggered by 8 k-chunks
// share one H stream; epilogues (warps 2-7) overlap the other half's MMAs.
// warp0 lane0 = MMA dispatcher, warp1 lane0 = TMA producer.
// X fed raw fp32 (HW tf32 truncation); H pre-rounded RN->tf32 in build_H.
// ============================================================================

#define N_F    512
#define KC     32          // K elems per chunk = 128 bytes = SW128 row
#define MT     256
#define NSTAGE 3
#define GRID   148
#define M_BLKS 1024        // 131072 / 128

__device__ float g_H[N_F * N_F];   // precomputed H (tf32-rounded fp32 bits)

#if defined(__CUDA_ARCH__) && (defined(__CUDA_ARCH_FEAT_SM103_ALL) || \
    defined(__CUDA_ARCH_FEAT_SM100_ALL) || defined(__CUDA_ARCH_FEAT_SM101_ALL))
#define HAS_TCGEN05 1
#else
#define HAS_TCGEN05 0
#endif

// ---------------- smem layout (dynamic), tcgen05 path ----------------
#define OFF_TPTR    0
#define OFF_FULL(s) (8 + 8 * (s))
#define OFF_DONE(s) (40 + 8 * (s))
#define OFF_EPI_A   64
#define OFF_EPI_B   72
#define OFF_DFREE_A 80
#define OFF_DFREE_B 88
#define OFF_STG(s)  (1024 + (s) * 65536)   // X_A 16KB | X_B 16KB | H 32KB
#define SMEM_BYTES  (1024 + NSTAGE * 65536)

// idesc: kind::tf32, D=F32(1<<4), A=TF32(2<<7), B=TF32(2<<10), N=256, M=128
#define IDESC_TF32_N256 ((1u << 4) | (2u << 7) | (2u << 10) | ((256u / 8u) << 17) | ((128u / 16u) << 24))

// K-major SW128 smem descriptor base: layout=SW128(2), version=1, SBO=64, LBO=1
static __device__ __host__ constexpr uint64_t DESC_BASE_SW128 =
    (uint64_t(2) << 61) | (uint64_t(1) << 46) | (uint64_t(64) << 32) | (uint64_t(1) << 16);

__device__ __forceinline__ uint32_t s2u(const void* p) {
    uint32_t a;
    asm("{ .reg .u64 t; cvta.to.shared.u64 t, %1; cvt.u32.u64 %0, t; }" : "=r"(a) : "l"(p));
    return a;
}

#define MBAR_INIT(addr, cnt) \
    asm volatile("mbarrier.init.shared.b64 [%0], %1;" :: "r"(addr), "r"(cnt) : "memory")

#define MBAR_ARRIVE(addr) \
    asm volatile("mbarrier.arrive.shared.b64 _, [%0];" :: "r"(addr) : "memory")

#define MBAR_EXPECT_TX(addr, bytes) \
    asm volatile("mbarrier.arrive.expect_tx.shared.b64 _, [%0], %1;" :: "r"(addr), "r"(bytes) : "memory")

#define MBAR_WAIT(addr, parity) do {                                           \
    uint32_t _mb = (addr); uint32_t _ph = (parity); uint32_t _dn;              \
    asm volatile("{\n\t.reg .pred p;\n\t"                                      \
        "mbarrier.try_wait.parity.acquire.cta.shared::cta.b64 p, [%1], %2;\n\t"\
        "selp.b32 %0, 1, 0, p;\n\t}" : "=r"(_dn) : "r"(_mb), "r"(_ph) : "memory"); \
    while (!_dn) {                                                             \
        asm volatile("{\n\t.reg .pred p;\n\t"                                  \
            "mbarrier.try_wait.parity.acquire.cta.shared::cta.b64 p, [%1], %2, 0x989680;\n\t" \
            "selp.b32 %0, 1, 0, p;\n\t}" : "=r"(_dn) : "r"(_mb), "r"(_ph) : "memory"); \
    }                                                                          \
} while (0)

#define TMA2D(smem, map, cx, cy, mbar)                                         \
    asm volatile("cp.async.bulk.tensor.2d.shared::cta.global.tile.mbarrier::complete_tx::bytes " \
        "[%0], [%1, {%2, %3}], [%4];"                                          \
        :: "r"(smem), "l"(map), "r"(cx), "r"(cy), "r"(mbar) : "memory")

#define MMA_TF32(dst, adsc, bdsc, en)                                          \
    asm volatile("{\n\t.reg .pred p;\n\tsetp.ne.u32 p, %5, 0;\n\t"             \
        "tcgen05.mma.cta_group::1.kind::tf32 [%0], %1, %2, %3, {%4,%4,%4,%4}, p;\n\t}" \
        :: "r"(dst), "l"(adsc), "l"(bdsc), "r"(IDESC_TF32_N256), "r"(0u), "r"(en) : "memory")

#define TC_COMMIT(mbar)                                                        \
    asm volatile("tcgen05.commit.cta_group::1.mbarrier::arrive::one.shared::cluster.b64 [%0];" \
        :: "r"(mbar) : "memory")

// ---------------------------------------------------------------------------
// H precompute: H[r=a*64+b][k=c*64+d] = sum_i A[i,a,c]*S[i,b,d], RN->tf32
// ---------------------------------------------------------------------------
__global__ void build_H(const float* __restrict__ A, const float* __restrict__ S) {
    int r = blockIdx.x;     // 0..511
    int k = threadIdx.x;    // 0..511
    int a = r >> 6, bb = r & 63, c = k >> 6, d = k & 63;
    float acc = 0.f;
#pragma unroll
    for (int i = 0; i < 8; i++)
        acc = fmaf(A[i * 64 + a * 8 + c], S[i * 4096 + bb * 64 + d], acc);
    uint32_t t;
    asm("cvt.rna.tf32.f32 %0, %1;" : "=r"(t) : "f"(acc));
    g_H[r * N_F + k] = __uint_as_float(t);
}

// ---------------------------------------------------------------------------
// Main GEMM kernel
// ---------------------------------------------------------------------------
__global__ void __launch_bounds__(256, 1) phm_gemm(
    const float* __restrict__ x,
    const float* __restrict__ bias, float* __restrict__ out,
    int ntiles,
    const __grid_constant__ CUtensorMap mx,
    const __grid_constant__ CUtensorMap mh)
{
    int bid = blockIdx.x;

#if HAS_TCGEN05
    // =================== tcgen05 TF32 path (sm_103a) =====================
    (void)x; (void)ntiles;
    extern __shared__ char smem_raw[];
    uint32_t sb = s2u(smem_raw);
    int tid = threadIdx.x, wid = tid >> 5, lid = tid & 31;

    // per-CTA m-block list per phase: m_blk = bid + 148*j, j < cnt
    int cnt = 1 + (M_BLKS - 1 - bid) / GRID;
    int nA = (cnt + 1) >> 1, nB = cnt >> 1;
    int P = 16 * nA;
    if (16 * nB + 8 > P) P = 16 * nB + 8;

    if (wid == 0) {
        asm volatile("tcgen05.alloc.cta_group::1.sync.aligned.shared::cta.b32 [%0], %1;"
                     :: "r"(sb + OFF_TPTR), "r"(512) : "memory");
        asm volatile("tcgen05.relinquish_alloc_permit.cta_group::1.sync.aligned;");
    }
    if (tid == 0) {
#pragma unroll
        for (int s = 0; s < NSTAGE; s++) {
            MBAR_INIT(sb + OFF_FULL(s), 1);
            MBAR_INIT(sb + OFF_DONE(s), 1);
        }
        MBAR_INIT(sb + OFF_EPI_A, 1);
        MBAR_INIT(sb + OFF_EPI_B, 1);
        MBAR_INIT(sb + OFF_DFREE_A, 6);
        MBAR_INIT(sb + OFF_DFREE_B, 6);
    }
    __syncthreads();
    uint32_t tmem;
    asm volatile("ld.shared.b32 %0, [%1];" : "=r"(tmem) : "r"(sb + OFF_TPTR));

    if (wid == 0 && lid == 0) {
        // ---------------- MMA dispatcher ----------------
        uint64_t dA[NSTAGE], dB[NSTAGE], dH[NSTAGE];
#pragma unroll
        for (int s = 0; s < NSTAGE; s++) {
            dA[s] = DESC_BASE_SW128 | (((sb + OFF_STG(s))         >> 4) & 0x3FFF);
            dB[s] = DESC_BASE_SW128 | (((sb + OFF_STG(s) + 16384) >> 4) & 0x3FFF);
            dH[s] = DESC_BASE_SW128 | (((sb + OFF_STG(s) + 32768) >> 4) & 0x3FFF);
        }
        int cs = 0, ph = 0;
        int uA = 0, uB = 0;   // D-buffer use counts (across phases)
        for (int phase = 0; phase < 2; phase++) {
            for (int p = 0; p < P; p++) {
                int k = p & 15;
                int iA = p >> 4;
                int iB = (p - 8) >> 4;
                int aA = (iA < nA);
                int aB = (p >= 8) && (iB < nB);

                MBAR_WAIT(sb + OFF_FULL(cs), ph);

                if (aA) {
                    if (k == 0) {
                        if (uA > 0) {
                            MBAR_WAIT(sb + OFF_DFREE_A, (uA - 1) & 1);
                            asm volatile("tcgen05.fence::after_thread_sync;" ::: "memory");
                        }
                        uA++;
                    }
#pragma unroll
                    for (int ks = 0; ks < 4; ks++) {
                        uint32_t en = (k != 0 || ks != 0) ? 1u : 0u;
                        MMA_TF32(tmem, dA[cs] + 2 * ks, dH[cs] + 2 * ks, en);
                    }
                }
                if (aB) {
                    if (k == 8) {
                        if (uB > 0) {
                            MBAR_WAIT(sb + OFF_DFREE_B, (uB - 1) & 1);
                            asm volatile("tcgen05.fence::after_thread_sync;" ::: "memory");
                        }
                        uB++;
                    }
#pragma unroll
                    for (int ks = 0; ks < 4; ks++) {
                        uint32_t en = (k != 8 || ks != 0) ? 1u : 0u;
                        MMA_TF32(tmem + 256, dB[cs] + 2 * ks, dH[cs] + 2 * ks, en);
                    }
                }
                TC_COMMIT(sb + OFF_DONE(cs));
                if (aA && k == 15) TC_COMMIT(sb + OFF_EPI_A);
                if (aB && k == 7)  TC_COMMIT(sb + OFF_EPI_B);
                if (++cs == NSTAGE) { cs = 0; ph ^= 1; }
            }
        }
    } else if (wid == 1 && lid == 0) {
        // ---------------- TMA producer ----------------
        int cs = 0, ph = 0, filled = 0;
        for (int phase = 0; phase < 2; phase++) {
            for (int p = 0; p < P; p++) {
                int k = p & 15;
                int iA = p >> 4;
                int iB = (p - 8) >> 4;
                int aA = (iA < nA);
                int aB = (p >= 8) && (iB < nB);

                if (filled >= NSTAGE)
                    MBAR_WAIT(sb + OFF_DONE(cs), ph ^ 1);
                uint32_t bytes = 32768u + (aA ? 16384u : 0u) + (aB ? 16384u : 0u);
                MBAR_EXPECT_TX(sb + OFF_FULL(cs), bytes);
                if (aA)
                    TMA2D(sb + OFF_STG(cs), &mx, k * KC,
                          (bid + GRID * (2 * iA)) * 128, sb + OFF_FULL(cs));
                if (aB)
                    TMA2D(sb + OFF_STG(cs) + 16384, &mx, k * KC,
                          (bid + GRID * (2 * iB + 1)) * 128, sb + OFF_FULL(cs));
                TMA2D(sb + OFF_STG(cs) + 32768, &mh, k * KC, phase * 256, sb + OFF_FULL(cs));
                filled++;
                if (++cs == NSTAGE) { cs = 0; ph ^= 1; }
            }
        }
    } else if (wid >= 2) {
        // ---------------- epilogue warps (2..7) ----------------
        // subpartition coverage: sp0=warp4, sp1=warp5, sp2=warps2/6, sp3=warps3/7
        int sp = wid & 3;
        int nch = (sp < 2) ? 8 : 4;
        int ch0 = (sp < 2) ? 0 : ((wid >= 6) ? 4 : 0);
        int uA = 0, uB = 0;
        for (int phase = 0; phase < 2; phase++) {
            for (int j = 0; j < cnt; j++) {
                int buf = j & 1;
                int m_blk = bid + GRID * j;
                uint32_t epib  = sb + (buf ? OFF_EPI_B : OFF_EPI_A);
                uint32_t dfrb  = sb + (buf ? OFF_DFREE_B : OFF_DFREE_A);
                int u = buf ? uB : uA;
                MBAR_WAIT(epib, u & 1);
                asm volatile("tcgen05.fence::after_thread_sync;" ::: "memory");

                float* orow = out + (size_t)(m_blk * 128 + sp * 32 + lid) * N_F + phase * 256;
                uint32_t tb = tmem + buf * 256;
                for (int c = 0; c < nch; c++) {
                    int c0 = (ch0 + c) * 32;
                    uint32_t r[32];
                    asm volatile(
                        "tcgen05.ld.sync.aligned.32x32b.x32.b32 "
                        "{%0, %1, %2, %3, %4, %5, %6, %7, "
                        " %8, %9, %10, %11, %12, %13, %14, %15, "
                        " %16, %17, %18, %19, %20, %21, %22, %23, "
                        " %24, %25, %26, %27, %28, %29, %30, %31}, [%32];"
                        : "=r"(r[0]),  "=r"(r[1]),  "=r"(r[2]),  "=r"(r[3]),
                          "=r"(r[4]),  "=r"(r[5]),  "=r"(r[6]),  "=r"(r[7]),
                          "=r"(r[8]),  "=r"(r[9]),  "=r"(r[10]), "=r"(r[11]),
                          "=r"(r[12]), "=r"(r[13]), "=r"(r[14]), "=r"(r[15]),
                          "=r"(r[16]), "=r"(r[17]), "=r"(r[18]), "=r"(r[19]),
                          "=r"(r[20]), "=r"(r[21]), "=r"(r[22]), "=r"(r[23]),
                          "=r"(r[24]), "=r"(r[25]), "=r"(r[26]), "=r"(r[27]),
                          "=r"(r[28]), "=r"(r[29]), "=r"(r[30]), "=r"(r[31])
                        : "r"(tb + c0));
                    asm volatile("tcgen05.wait::ld.sync.aligned;" ::: "memory");
#pragma unroll
                    for (int q = 0; q < 8; q++) {
                        float4 bv = *reinterpret_cast<const float4*>(bias + phase * 256 + c0 + q * 4);
                        float4 v;
                        v.x = __uint_as_float(r[q * 4 + 0]) + bv.x;
                        v.y = __uint_as_float(r[q * 4 + 1]) + bv.y;
                        v.z = __uint_as_float(r[q * 4 + 2]) + bv.z;
                        v.w = __uint_as_float(r[q * 4 + 3]) + bv.w;
                        *reinterpret_cast<float4*>(orow + c0 + q * 4) = v;
                    }
                }
                asm volatile("tcgen05.fence::before_thread_sync;" ::: "memory");
                if (lid == 0) MBAR_ARRIVE(dfrb);
                if (buf) uB++; else uA++;
            }
        }
    }

    __syncthreads();
    if (wid == 0) {
        asm volatile("tcgen05.dealloc.cta_group::1.sync.aligned.b32 %0, %1;"
                     :: "r"(tmem), "r"(512));
    }

#else
    // =================== SIMT fp32 fallback (non-'a' pass) ================
    (void)mx; (void)mh;
    extern __shared__ char smem_raw[];
    float* Xs = reinterpret_cast<float*>(smem_raw);          // [128][33]
    float* Hs = Xs + 128 * 33;                               // [64][33]

    int tid = threadIdx.x;
    int ty = tid >> 4, tx = tid & 15;

    for (int g = bid; g < ntiles; g += GRID) {
        int m0 = (g >> 1) * MT;
        int nb = g & 1;
        for (int half = 0; half < 2; half++) {
            int m0h = m0 + half * 128;
            for (int nc = 0; nc < 4; nc++) {
                int col0 = nb * 256 + nc * 64;
                float acc[8][4];
#pragma unroll
                for (int i = 0; i < 8; i++)
#pragma unroll
                    for (int j = 0; j < 4; j++) acc[i][j] = 0.f;

                for (int kb = 0; kb < 16; kb++) {
#pragma unroll
                    for (int it = 0; it < 16; it++) {
                        int idx = tid + it * 256;
                        int r = idx >> 5, k = idx & 31;
                        Xs[r * 33 + k] = x[(size_t)(m0h + r) * N_F + kb * 32 + k];
                    }
#pragma unroll
                    for (int it = 0; it < 8; it++) {
                        int idx = tid + it * 256;
                        int r = idx >> 5, k = idx & 31;
                        Hs[r * 33 + k] = g_H[(size_t)(col0 + r) * N_F + kb * 32 + k];
                    }
                    __syncthreads();
#pragma unroll
                    for (int k = 0; k < 32; k++) {
                        float a8[8], b4[4];
#pragma unroll
                        for (int i = 0; i < 8; i++) a8[i] = Xs[(ty * 8 + i) * 33 + k];
#pragma unroll
                        for (int j = 0; j < 4; j++) b4[j] = Hs[(tx * 4 + j) * 33 + k];
#pragma unroll
                        for (int i = 0; i < 8; i++)
#pragma unroll
                            for (int j = 0; j < 4; j++)
                                acc[i][j] = fmaf(a8[i], b4[j], acc[i][j]);
                    }
                    __syncthreads();
                }
#pragma unroll
                for (int i = 0; i < 8; i++)
#pragma unroll
                    for (int j = 0; j < 4; j++) {
                        int col = col0 + tx * 4 + j;
                        out[(size_t)(m0h + ty * 8 + i) * N_F + col] = acc[i][j] + bias[col];
                    }
            }
        }
    }
#endif
}

// ---------------------------------------------------------------------------
// Host launcher
// ---------------------------------------------------------------------------
typedef CUresult (*PFN_encodeTiled)(
    CUtensorMap*, CUtensorMapDataType, cuuint32_t, void*,
    const cuuint64_t*, const cuuint64_t*, const cuuint32_t*, const cuuint32_t*,
    CUtensorMapInterleave, CUtensorMapSwizzle, CUtensorMapL2promotion,
    CUtensorMapFloatOOBfill);

extern "C" void kernel_launch(void* const* d_in, const int* in_sizes, int n_in,
                              void* d_out, int out_size) {
    const float* x    = (const float*)d_in[0];
    const float* A    = (const float*)d_in[1];
    const float* S    = (const float*)d_in[2];
    const float* bias = (const float*)d_in[3];
    float* out = (float*)d_out;

    long Mrows = (long)in_sizes[0] / N_F;   // 131072
    int ntiles = (int)(Mrows / MT) * 2;     // 1024 (fallback path only)

    build_H<<<N_F, N_F>>>(A, S);

    void* hptr = nullptr;
    cudaGetSymbolAddress(&hptr, g_H);

    // Resolve cuTensorMapEncodeTiled via the runtime (no -lcuda needed).
    PFN_encodeTiled enc = nullptr;
    {
        cudaDriverEntryPointQueryResult st;
        cudaGetDriverEntryPointByVersion("cuTensorMapEncodeTiled", (void**)&enc,
                                         12050, cudaEnableDefault, &st);
    }

    CUtensorMap mx{}, mh{};
    if (enc) {
        {
            cuuint64_t dims[2]    = {(cuuint64_t)N_F, (cuuint64_t)Mrows};
            cuuint64_t strides[1] = {(cuuint64_t)N_F * 4};
            cuuint32_t box[2]     = {KC, 128};       // 128B x 128 rows (X sub-tile)
            cuuint32_t es[2]      = {1, 1};
            enc(&mx, CU_TENSOR_MAP_DATA_TYPE_FLOAT32, 2, (void*)x,
                dims, strides, box, es,
                CU_TENSOR_MAP_INTERLEAVE_NONE, CU_TENSOR_MAP_SWIZZLE_128B,
                CU_TENSOR_MAP_L2_PROMOTION_L2_128B, CU_TENSOR_MAP_FLOAT_OOB_FILL_NONE);
        }
        {
            cuuint64_t dims[2]    = {(cuuint64_t)N_F, (cuuint64_t)N_F};
            cuuint64_t strides[1] = {(cuuint64_t)N_F * 4};
            cuuint32_t box[2]     = {KC, 256};       // 128B x 256 rows (H half)
            cuuint32_t es[2]      = {1, 1};
            enc(&mh, CU_TENSOR_MAP_DATA_TYPE_FLOAT32, 2, hptr,
                dims, strides, box, es,
                CU_TENSOR_MAP_INTERLEAVE_NONE, CU_TENSOR_MAP_SWIZZLE_128B,
                CU_TENSOR_MAP_L2_PROMOTION_L2_128B, CU_TENSOR_MAP_FLOAT_OOB_FILL_NONE);
        }
    }

    cudaFuncSetAttribute(phm_gemm, cudaFuncAttributeMaxDynamicSharedMemorySize, SMEM_BYTES);
    phm_gemm<<<GRID, 256, SMEM_BYTES>>>(x, bias, out, ntiles, mx, mh);
}

// round 8
// speedup vs baseline: 1.1030x; 1.1030x over previous
#include <cuda_runtime.h>
#include <cuda.h>
#include <cstdint>

// ============================================================================
// PHM8Linear: out[131072,512] = X[131072,512] @ H[512,512]^T + bias
// H[a*64+b][c*64+d] = sum_i A[i,a,c] * S[i,b,d]
// tcgen05 TF32 SS GEMM, persistent grid=148.
// CTA pair {2c,2c+1} handles nb=0/1 of the same m-tile sequence (X L2 reuse).
// Within a CTA: sub-tile A (rows m0..+127, TMEM cols 0-255) and sub-tile B
// (rows m0+128..+255, cols 256-511) staggered by 8 positions on ONE periodic
// H stream (H depends only on (nb,k)); epilogues alternate every 8 positions
// and overlap the other half's MMAs. warp0=dispatcher, warp1=producer,
// warps 2-7=epilogue. X raw fp32 (HW tf32 truncate); H pre-rounded RN.
// ============================================================================

#define N_F    512
#define KC     32          // K elems per chunk = 128 bytes = SW128 row
#define NSTAGE 3
#define GRID   148
#define NPAIR  74          // GRID/2 m-tile streams
#define M_TILES 512        // 131072/256

__device__ float g_H[N_F * N_F];   // precomputed H (tf32-rounded fp32 bits)

#if defined(__CUDA_ARCH__) && (defined(__CUDA_ARCH_FEAT_SM103_ALL) || \
    defined(__CUDA_ARCH_FEAT_SM100_ALL) || defined(__CUDA_ARCH_FEAT_SM101_ALL))
#define HAS_TCGEN05 1
#else
#define HAS_TCGEN05 0
#endif

// ---------------- smem layout (dynamic), tcgen05 path ----------------
#define OFF_TPTR    0
#define OFF_FULL(s) (8 + 8 * (s))
#define OFF_DONE(s) (40 + 8 * (s))
#define OFF_EPI_A   64
#define OFF_EPI_B   72
#define OFF_DFREE_A 80
#define OFF_DFREE_B 88
#define OFF_STG(s)  (1024 + (s) * 65536)   // X_A 16KB | X_B 16KB | H 32KB
#define SMEM_BYTES  (1024 + NSTAGE * 65536)

// idesc: kind::tf32, D=F32(1<<4), A=TF32(2<<7), B=TF32(2<<10), N=256, M=128
#define IDESC_TF32_N256 ((1u << 4) | (2u << 7) | (2u << 10) | ((256u / 8u) << 17) | ((128u / 16u) << 24))

// K-major SW128 smem descriptor base: layout=SW128(2), version=1, SBO=64, LBO=1
static __device__ __host__ constexpr uint64_t DESC_BASE_SW128 =
    (uint64_t(2) << 61) | (uint64_t(1) << 46) | (uint64_t(64) << 32) | (uint64_t(1) << 16);

__device__ __forceinline__ uint32_t s2u(const void* p) {
    uint32_t a;
    asm("{ .reg .u64 t; cvta.to.shared.u64 t, %1; cvt.u32.u64 %0, t; }" : "=r"(a) : "l"(p));
    return a;
}

#define MBAR_INIT(addr, cnt) \
    asm volatile("mbarrier.init.shared.b64 [%0], %1;" :: "r"(addr), "r"(cnt) : "memory")

#define MBAR_ARRIVE(addr) \
    asm volatile("mbarrier.arrive.shared.b64 _, [%0];" :: "r"(addr) : "memory")

#define MBAR_EXPECT_TX(addr, bytes) \
    asm volatile("mbarrier.arrive.expect_tx.shared.b64 _, [%0], %1;" :: "r"(addr), "r"(bytes) : "memory")

#define MBAR_WAIT(addr, parity) do {                                           \
    uint32_t _mb = (addr); uint32_t _ph = (parity); uint32_t _dn;              \
    asm volatile("{\n\t.reg .pred p;\n\t"                                      \
        "mbarrier.try_wait.parity.acquire.cta.shared::cta.b64 p, [%1], %2;\n\t"\
        "selp.b32 %0, 1, 0, p;\n\t}" : "=r"(_dn) : "r"(_mb), "r"(_ph) : "memory"); \
    while (!_dn) {                                                             \
        asm volatile("{\n\t.reg .pred p;\n\t"                                  \
            "mbarrier.try_wait.parity.acquire.cta.shared::cta.b64 p, [%1], %2, 0x989680;\n\t" \
            "selp.b32 %0, 1, 0, p;\n\t}" : "=r"(_dn) : "r"(_mb), "r"(_ph) : "memory"); \
    }                                                                          \
} while (0)

#define TMA2D(smem, map, cx, cy, mbar)                                         \
    asm volatile("cp.async.bulk.tensor.2d.shared::cta.global.tile.mbarrier::complete_tx::bytes " \
        "[%0], [%1, {%2, %3}], [%4];"                                          \
        :: "r"(smem), "l"(map), "r"(cx), "r"(cy), "r"(mbar) : "memory")

#define MMA_TF32(dst, adsc, bdsc, en)                                          \
    asm volatile("{\n\t.reg .pred p;\n\tsetp.ne.u32 p, %5, 0;\n\t"             \
        "tcgen05.mma.cta_group::1.kind::tf32 [%0], %1, %2, %3, {%4,%4,%4,%4}, p;\n\t}" \
        :: "r"(dst), "l"(adsc), "l"(bdsc), "r"(IDESC_TF32_N256), "r"(0u), "r"(en) : "memory")

#define TC_COMMIT(mbar)                                                        \
    asm volatile("tcgen05.commit.cta_group::1.mbarrier::arrive::one.shared::cluster.b64 [%0];" \
        :: "r"(mbar) : "memory")

// ---------------------------------------------------------------------------
// H precompute: H[r=a*64+b][k=c*64+d] = sum_i A[i,a,c]*S[i,b,d], RN->tf32
// ---------------------------------------------------------------------------
__global__ void build_H(const float* __restrict__ A, const float* __restrict__ S) {
    int r = blockIdx.x;     // 0..511
    int k = threadIdx.x;    // 0..511
    int a = r >> 6, bb = r & 63, c = k >> 6, d = k & 63;
    float acc = 0.f;
#pragma unroll
    for (int i = 0; i < 8; i++)
        acc = fmaf(A[i * 64 + a * 8 + c], S[i * 4096 + bb * 64 + d], acc);
    uint32_t t;
    asm("cvt.rna.tf32.f32 %0, %1;" : "=r"(t) : "f"(acc));
    g_H[r * N_F + k] = __uint_as_float(t);
}

// ---------------------------------------------------------------------------
// Main GEMM kernel
// ---------------------------------------------------------------------------
__global__ void __launch_bounds__(256, 1) phm_gemm(
    const float* __restrict__ x,
    const float* __restrict__ bias, float* __restrict__ out,
    int ntiles,
    const __grid_constant__ CUtensorMap mx,
    const __grid_constant__ CUtensorMap mh)
{
    int bid = blockIdx.x;

#if HAS_TCGEN05
    // =================== tcgen05 TF32 path (sm_103a) =====================
    (void)x; (void)ntiles;
    extern __shared__ char smem_raw[];
    uint32_t sb = s2u(smem_raw);
    int tid = threadIdx.x, wid = tid >> 5, lid = tid & 31;

    int c  = bid >> 1;          // m-tile stream (0..73)
    int nb = bid & 1;           // N half (fixed per CTA)
    int cnt = 1 + (M_TILES - 1 - c) / NPAIR;   // tiles for this stream
    int P = 16 * cnt + 8;                      // stream positions (tail for B)

    if (wid == 0) {
        asm volatile("tcgen05.alloc.cta_group::1.sync.aligned.shared::cta.b32 [%0], %1;"
                     :: "r"(sb + OFF_TPTR), "r"(512) : "memory");
        asm volatile("tcgen05.relinquish_alloc_permit.cta_group::1.sync.aligned;");
    }
    if (tid == 0) {
#pragma unroll
        for (int s = 0; s < NSTAGE; s++) {
            MBAR_INIT(sb + OFF_FULL(s), 1);
            MBAR_INIT(sb + OFF_DONE(s), 1);
        }
        MBAR_INIT(sb + OFF_EPI_A, 1);
        MBAR_INIT(sb + OFF_EPI_B, 1);
        MBAR_INIT(sb + OFF_DFREE_A, 6);
        MBAR_INIT(sb + OFF_DFREE_B, 6);
    }
    __syncthreads();
    uint32_t tmem;
    asm volatile("ld.shared.b32 %0, [%1];" : "=r"(tmem) : "r"(sb + OFF_TPTR));

    if (wid == 0 && lid == 0) {
        // ---------------- MMA dispatcher ----------------
        uint64_t dA[NSTAGE], dB[NSTAGE], dH[NSTAGE];
#pragma unroll
        for (int s = 0; s < NSTAGE; s++) {
            dA[s] = DESC_BASE_SW128 | (((sb + OFF_STG(s))         >> 4) & 0x3FFF);
            dB[s] = DESC_BASE_SW128 | (((sb + OFF_STG(s) + 16384) >> 4) & 0x3FFF);
            dH[s] = DESC_BASE_SW128 | (((sb + OFF_STG(s) + 32768) >> 4) & 0x3FFF);
        }
        int cs = 0, ph = 0;
        for (int p = 0; p < P; p++) {
            int k  = p & 15;
            int j  = p >> 4;
            int jB = (p - 8) >> 4;
            int aA = (j < cnt);
            int aB = (p >= 8) && (jB < cnt);

            MBAR_WAIT(sb + OFF_FULL(cs), ph);

            if (k == 0) {
                // B mid-window: feed the pipe before A's D-free wait
                if (aB) {
#pragma unroll
                    for (int ks = 0; ks < 4; ks++)
                        MMA_TF32(tmem + 256, dB[cs] + 2 * ks, dH[cs] + 2 * ks, 1u);
                }
                if (aA) {
                    if (j > 0) {
                        MBAR_WAIT(sb + OFF_DFREE_A, (j - 1) & 1);
                        asm volatile("tcgen05.fence::after_thread_sync;" ::: "memory");
                    }
#pragma unroll
                    for (int ks = 0; ks < 4; ks++)
                        MMA_TF32(tmem, dA[cs] + 2 * ks, dH[cs] + 2 * ks, ks ? 1u : 0u);
                }
            } else if (k == 8) {
                if (aA) {
#pragma unroll
                    for (int ks = 0; ks < 4; ks++)
                        MMA_TF32(tmem, dA[cs] + 2 * ks, dH[cs] + 2 * ks, 1u);
                }
                if (aB) {
                    if (jB > 0) {
                        MBAR_WAIT(sb + OFF_DFREE_B, (jB - 1) & 1);
                        asm volatile("tcgen05.fence::after_thread_sync;" ::: "memory");
                    }
#pragma unroll
                    for (int ks = 0; ks < 4; ks++)
                        MMA_TF32(tmem + 256, dB[cs] + 2 * ks, dH[cs] + 2 * ks, ks ? 1u : 0u);
                }
            } else {
                if (aA) {
#pragma unroll
                    for (int ks = 0; ks < 4; ks++)
                        MMA_TF32(tmem, dA[cs] + 2 * ks, dH[cs] + 2 * ks, 1u);
                }
                if (aB) {
#pragma unroll
                    for (int ks = 0; ks < 4; ks++)
                        MMA_TF32(tmem + 256, dB[cs] + 2 * ks, dH[cs] + 2 * ks, 1u);
                }
            }
            TC_COMMIT(sb + OFF_DONE(cs));
            if (aA && k == 15) TC_COMMIT(sb + OFF_EPI_A);
            if (aB && k == 7)  TC_COMMIT(sb + OFF_EPI_B);
            if (++cs == NSTAGE) { cs = 0; ph ^= 1; }
        }
    } else if (wid == 1 && lid == 0) {
        // ---------------- TMA producer ----------------
        int cs = 0, ph = 0, filled = 0;
        for (int p = 0; p < P; p++) {
            int k  = p & 15;
            int j  = p >> 4;
            int jB = (p - 8) >> 4;
            int aA = (j < cnt);
            int aB = (p >= 8) && (jB < cnt);

            if (filled >= NSTAGE)
                MBAR_WAIT(sb + OFF_DONE(cs), ph ^ 1);
            uint32_t bytes = 32768u + (aA ? 16384u : 0u) + (aB ? 16384u : 0u);
            MBAR_EXPECT_TX(sb + OFF_FULL(cs), bytes);
            if (aA)
                TMA2D(sb + OFF_STG(cs), &mx, k * KC,
                      (c + NPAIR * j) * 256, sb + OFF_FULL(cs));
            if (aB)
                TMA2D(sb + OFF_STG(cs) + 16384, &mx, k * KC,
                      (c + NPAIR * jB) * 256 + 128, sb + OFF_FULL(cs));
            TMA2D(sb + OFF_STG(cs) + 32768, &mh, k * KC, nb * 256, sb + OFF_FULL(cs));
            filled++;
            if (++cs == NSTAGE) { cs = 0; ph ^= 1; }
        }
    } else if (wid >= 2) {
        // ---------------- epilogue warps (2..7) ----------------
        // subpartition coverage: sp0=warp4, sp1=warp5, sp2=warps2/6, sp3=warps3/7
        int sp = wid & 3;
        int nch = (sp < 2) ? 8 : 4;
        int ch0 = (sp < 2) ? 0 : ((wid >= 6) ? 4 : 0);
        for (int j = 0; j < cnt; j++) {
#pragma unroll
            for (int half = 0; half < 2; half++) {   // 0 = A event, 1 = B event
                uint32_t epib = sb + (half ? OFF_EPI_B : OFF_EPI_A);
                uint32_t dfrb = sb + (half ? OFF_DFREE_B : OFF_DFREE_A);
                MBAR_WAIT(epib, j & 1);
                asm volatile("tcgen05.fence::after_thread_sync;" ::: "memory");

                size_t row = (size_t)((c + NPAIR * j) * 256 + half * 128 + sp * 32 + lid);
                float* orow = out + row * N_F + nb * 256;
                uint32_t tb = tmem + half * 256;
                for (int cc = 0; cc < nch; cc++) {
                    int c0 = (ch0 + cc) * 32;
                    uint32_t r[32];
                    asm volatile(
                        "tcgen05.ld.sync.aligned.32x32b.x32.b32 "
                        "{%0, %1, %2, %3, %4, %5, %6, %7, "
                        " %8, %9, %10, %11, %12, %13, %14, %15, "
                        " %16, %17, %18, %19, %20, %21, %22, %23, "
                        " %24, %25, %26, %27, %28, %29, %30, %31}, [%32];"
                        : "=r"(r[0]),  "=r"(r[1]),  "=r"(r[2]),  "=r"(r[3]),
                          "=r"(r[4]),  "=r"(r[5]),  "=r"(r[6]),  "=r"(r[7]),
                          "=r"(r[8]),  "=r"(r[9]),  "=r"(r[10]), "=r"(r[11]),
                          "=r"(r[12]), "=r"(r[13]), "=r"(r[14]), "=r"(r[15]),
                          "=r"(r[16]), "=r"(r[17]), "=r"(r[18]), "=r"(r[19]),
                          "=r"(r[20]), "=r"(r[21]), "=r"(r[22]), "=r"(r[23]),
                          "=r"(r[24]), "=r"(r[25]), "=r"(r[26]), "=r"(r[27]),
                          "=r"(r[28]), "=r"(r[29]), "=r"(r[30]), "=r"(r[31])
                        : "r"(tb + c0));
                    asm volatile("tcgen05.wait::ld.sync.aligned;" ::: "memory");
                    if (cc == nch - 1) {
                        // TMEM cols free (data in regs) -> release dispatcher early
                        asm volatile("tcgen05.fence::before_thread_sync;" ::: "memory");
                        if (lid == 0) MBAR_ARRIVE(dfrb);
                    }
#pragma unroll
                    for (int q = 0; q < 8; q++) {
                        float4 bv = *reinterpret_cast<const float4*>(bias + nb * 256 + c0 + q * 4);
                        float4 v;
                        v.x = __uint_as_float(r[q * 4 + 0]) + bv.x;
                        v.y = __uint_as_float(r[q * 4 + 1]) + bv.y;
                        v.z = __uint_as_float(r[q * 4 + 2]) + bv.z;
                        v.w = __uint_as_float(r[q * 4 + 3]) + bv.w;
                        *reinterpret_cast<float4*>(orow + c0 + q * 4) = v;
                    }
                }
            }
        }
    }

    __syncthreads();
    if (wid == 0) {
        asm volatile("tcgen05.dealloc.cta_group::1.sync.aligned.b32 %0, %1;"
                     :: "r"(tmem), "r"(512));
    }

#else
    // =================== SIMT fp32 fallback (non-'a' pass) ================
    (void)mx; (void)mh;
    extern __shared__ char smem_raw[];
    float* Xs = reinterpret_cast<float*>(smem_raw);          // [128][33]
    float* Hs = Xs + 128 * 33;                               // [64][33]

    int tid = threadIdx.x;
    int ty = tid >> 4, tx = tid & 15;

    for (int g = bid; g < ntiles; g += GRID) {
        int m0 = (g >> 1) * 256;
        int nb = g & 1;
        for (int half = 0; half < 2; half++) {
            int m0h = m0 + half * 128;
            for (int nc = 0; nc < 4; nc++) {
                int col0 = nb * 256 + nc * 64;
                float acc[8][4];
#pragma unroll
                for (int i = 0; i < 8; i++)
#pragma unroll
                    for (int j = 0; j < 4; j++) acc[i][j] = 0.f;

                for (int kb = 0; kb < 16; kb++) {
#pragma unroll
                    for (int it = 0; it < 16; it++) {
                        int idx = tid + it * 256;
                        int r = idx >> 5, k = idx & 31;
                        Xs[r * 33 + k] = x[(size_t)(m0h + r) * N_F + kb * 32 + k];
                    }
#pragma unroll
                    for (int it = 0; it < 8; it++) {
                        int idx = tid + it * 256;
                        int r = idx >> 5, k = idx & 31;
                        Hs[r * 33 + k] = g_H[(size_t)(col0 + r) * N_F + kb * 32 + k];
                    }
                    __syncthreads();
#pragma unroll
                    for (int k = 0; k < 32; k++) {
                        float a8[8], b4[4];
#pragma unroll
                        for (int i = 0; i < 8; i++) a8[i] = Xs[(ty * 8 + i) * 33 + k];
#pragma unroll
                        for (int j = 0; j < 4; j++) b4[j] = Hs[(tx * 4 + j) * 33 + k];
#pragma unroll
                        for (int i = 0; i < 8; i++)
#pragma unroll
                            for (int j = 0; j < 4; j++)
                                acc[i][j] = fmaf(a8[i], b4[j], acc[i][j]);
                    }
                    __syncthreads();
                }
#pragma unroll
                for (int i = 0; i < 8; i++)
#pragma unroll
                    for (int j = 0; j < 4; j++) {
                        int col = col0 + tx * 4 + j;
                        out[(size_t)(m0h + ty * 8 + i) * N_F + col] = acc[i][j] + bias[col];
                    }
            }
        }
    }
#endif
}

// ---------------------------------------------------------------------------
// Host launcher
// ---------------------------------------------------------------------------
typedef CUresult (*PFN_encodeTiled)(
    CUtensorMap*, CUtensorMapDataType, cuuint32_t, void*,
    const cuuint64_t*, const cuuint64_t*, const cuuint32_t*, const cuuint32_t*,
    CUtensorMapInterleave, CUtensorMapSwizzle, CUtensorMapL2promotion,
    CUtensorMapFloatOOBfill);

extern "C" void kernel_launch(void* const* d_in, const int* in_sizes, int n_in,
                              void* d_out, int out_size) {
    const float* x    = (const float*)d_in[0];
    const float* A    = (const float*)d_in[1];
    const float* S    = (const float*)d_in[2];
    const float* bias = (const float*)d_in[3];
    float* out = (float*)d_out;

    long Mrows = (long)in_sizes[0] / N_F;   // 131072
    int ntiles = (int)(Mrows / 256) * 2;    // fallback path only

    build_H<<<N_F, N_F>>>(A, S);

    void* hptr = nullptr;
    cudaGetSymbolAddress(&hptr, g_H);

    // Resolve cuTensorMapEncodeTiled via the runtime (no -lcuda needed).
    PFN_encodeTiled enc = nullptr;
    {
        cudaDriverEntryPointQueryResult st;
        cudaGetDriverEntryPointByVersion("cuTensorMapEncodeTiled", (void**)&enc,
                                         12050, cudaEnableDefault, &st);
    }

    CUtensorMap mx{}, mh{};
    if (enc) {
        {
            cuuint64_t dims[2]    = {(cuuint64_t)N_F, (cuuint64_t)Mrows};
            cuuint64_t strides[1] = {(cuuint64_t)N_F * 4};
            cuuint32_t box[2]     = {KC, 128};       // 128B x 128 rows (X sub-tile)
            cuuint32_t es[2]      = {1, 1};
            enc(&mx, CU_TENSOR_MAP_DATA_TYPE_FLOAT32, 2, (void*)x,
                dims, strides, box, es,
                CU_TENSOR_MAP_INTERLEAVE_NONE, CU_TENSOR_MAP_SWIZZLE_128B,
                CU_TENSOR_MAP_L2_PROMOTION_L2_128B, CU_TENSOR_MAP_FLOAT_OOB_FILL_NONE);
        }
        {
            cuuint64_t dims[2]    = {(cuuint64_t)N_F, (cuuint64_t)N_F};
            cuuint64_t strides[1] = {(cuuint64_t)N_F * 4};
            cuuint32_t box[2]     = {KC, 256};       // 128B x 256 rows (H half)
            cuuint32_t es[2]      = {1, 1};
            enc(&mh, CU_TENSOR_MAP_DATA_TYPE_FLOAT32, 2, hptr,
                dims, strides, box, es,
                CU_TENSOR_MAP_INTERLEAVE_NONE, CU_TENSOR_MAP_SWIZZLE_128B,
                CU_TENSOR_MAP_L2_PROMOTION_L2_128B, CU_TENSOR_MAP_FLOAT_OOB_FILL_NONE);
        }
    }

    cudaFuncSetAttribute(phm_gemm, cudaFuncAttributeMaxDynamicSharedMemorySize, SMEM_BYTES);
    phm_gemm<<<GRID, 256, SMEM_BYTES>>>(x, bias, out, ntiles, mx, mh);
}